// round 3
// baseline (speedup 1.0000x reference)
#include <cuda_runtime.h>
#include <math_constants.h>

#define IN_DIM   256
#define CODE_LEN 128
#define MEM_LEN  65536
#define GRID     592          // 148 SMs * 4 CTAs — co-resident by __launch_bounds__(256,4)
#define NTHREADS 256

// Output layout (flattened tuple, all f32):
#define OUT_MEM_OFF 1LL
#define OUT_MD_OFF  (1LL + (long long)MEM_LEN * CODE_LEN)
#define OUT_IDX_OFF (OUT_MD_OFF + (long long)MEM_LEN * IN_DIM)

// Scratch (device globals; statically armed, re-armed at end of each run)
__device__ float               g_colsum[IN_DIM];                  // zero-init
__device__ float               g_colsq[IN_DIM];                   // zero-init
__device__ __align__(16) float g_enc[CODE_LEN];
__device__ int                 g_minbits = 0x7f800000;            // +inf
__device__ unsigned long long  g_argmin  = 0xFFFFFFFFFFFFFFFFULL;
// Generational grid barrier (count self-resets; gen grows monotonically — replay-safe)
__device__ unsigned            g_bar_count = 0;
__device__ unsigned            g_bar_gen   = 0;

__device__ __forceinline__ void grid_barrier() {
    __threadfence();            // publish this thread's prior writes
    __syncthreads();
    if (threadIdx.x == 0) {
        unsigned gen = *(volatile unsigned*)&g_bar_gen;
        if (atomicAdd(&g_bar_count, 1) == GRID - 1) {
            g_bar_count = 0;
            __threadfence();
            atomicAdd(&g_bar_gen, 1);
        } else {
            while (*(volatile unsigned*)&g_bar_gen == gen) __nanosleep(64);
        }
    }
    __syncthreads();
    __threadfence();            // acquire side
}

__global__ void __launch_bounds__(NTHREADS, 4)
fused(const float* __restrict__ x,        const float4* __restrict__ mem4,
      const float4* __restrict__ md4,     const int* __restrict__ idx,
      const float* __restrict__ W,        const float* __restrict__ b,
      const int* __restrict__ count,      float* __restrict__ out) {
    const int tid    = threadIdx.x;
    const int gtid   = blockIdx.x * NTHREADS + tid;
    const int nthr   = GRID * NTHREADS;

    // ---------------- Phase A: all streaming ----------------
    // A1: mem_data [65536,256] — float4 read + copy + column sum/sumsq.
    //     stride*4 % 256 == 0  ->  this thread's 4 columns are fixed: (4*tid)&255
    {
        float* out_md = out + OUT_MD_OFF;
        const long long N4 = (long long)MEM_LEN * IN_DIM / 4;
        float s0 = 0, s1 = 0, s2 = 0, s3 = 0, q0 = 0, q1 = 0, q2 = 0, q3 = 0;
        for (long long i = gtid; i < N4; i += nthr) {
            float4 v = md4[i];
            float* o = out_md + i * 4;
            o[0] = v.x; o[1] = v.y; o[2] = v.z; o[3] = v.w;
            s0 += v.x; q0 += v.x * v.x;
            s1 += v.y; q1 += v.y * v.y;
            s2 += v.z; q2 += v.z * v.z;
            s3 += v.w; q3 += v.w * v.w;
        }
        __shared__ float sh_s[4][IN_DIM];
        __shared__ float sh_q[4][IN_DIM];
        int col = (4 * tid) & 255, grp = tid >> 6;
        sh_s[grp][col] = s0; sh_s[grp][col + 1] = s1; sh_s[grp][col + 2] = s2; sh_s[grp][col + 3] = s3;
        sh_q[grp][col] = q0; sh_q[grp][col + 1] = q1; sh_q[grp][col + 2] = q2; sh_q[grp][col + 3] = q3;
        __syncthreads();
        atomicAdd(&g_colsum[tid], sh_s[0][tid] + sh_s[1][tid] + sh_s[2][tid] + sh_s[3][tid]);
        atomicAdd(&g_colsq[tid],  sh_q[0][tid] + sh_q[1][tid] + sh_q[2][tid] + sh_q[3][tid]);
    }
    // A2: mem_idx copy + packed argmin (first-index tie-break)
    if (gtid < MEM_LEN) {
        int v = idx[gtid];
        out[OUT_IDX_OFF + gtid] = (float)v;
        unsigned long long key =
            ((unsigned long long)(unsigned)(v ^ 0x80000000) << 32) | (unsigned long long)gtid;
        #pragma unroll
        for (int off = 16; off; off >>= 1) {
            unsigned long long o = __shfl_xor_sync(0xFFFFFFFFu, key, off);
            key = (o < key) ? o : key;
        }
        if ((tid & 31) == 0) atomicMin(&g_argmin, key);
    }
    // A3: memory [65536,128] copy (independent of enc) — touched LAST so it's
    //     hot in L2 for the phase-C distance pass.
    {
        float* out_mem = out + OUT_MEM_OFF;
        const long long N4 = (long long)MEM_LEN * CODE_LEN / 4;
        for (long long i = gtid; i < N4; i += nthr) {
            float4 v = mem4[i];
            float* o = out_mem + i * 4;
            o[0] = v.x; o[1] = v.y; o[2] = v.z; o[3] = v.w;
        }
    }

    grid_barrier();   // stats complete

    // ---------------- Phase B: enc (blocks 0..127, one row each) ------------
    if (blockIdx.x < CODE_LEN) {
        int row = blockIdx.x;
        float mean = g_colsum[tid] * (1.0f / (float)MEM_LEN);
        float var  = (g_colsq[tid] - (float)MEM_LEN * mean * mean) * (1.0f / (float)(MEM_LEN - 1));
        float sd   = sqrtf(fmaxf(var, 0.0f));
        float nv   = (sd == 0.0f) ? 0.0f : (x[tid] - mean) / sd;
        float p    = nv * W[(long long)row * IN_DIM + tid];
        #pragma unroll
        for (int off = 16; off; off >>= 1) p += __shfl_xor_sync(0xFFFFFFFFu, p, off);
        __shared__ float red[8];
        if ((tid & 31) == 0) red[tid >> 5] = p;
        __syncthreads();
        if (tid == 0) {
            float a = b[row];
            #pragma unroll
            for (int i = 0; i < 8; i++) a += red[i];
            g_enc[row] = a;
        }
    }

    grid_barrier();   // enc visible

    // ---------------- Phase C: L1 distance (warp per row, L2-warm reads) ----
    {
        int lane  = tid & 31;
        int warp  = gtid >> 5;
        int nwarp = nthr >> 5;
        float4 e = reinterpret_cast<const float4*>(g_enc)[lane];
        float best = CUDART_INF_F;
        for (int row = warp; row < MEM_LEN; row += nwarp) {
            float4 v = mem4[(long long)row * 32 + lane];
            float d = fabsf(v.x - e.x) + fabsf(v.y - e.y) + fabsf(v.z - e.z) + fabsf(v.w - e.w);
            #pragma unroll
            for (int off = 16; off; off >>= 1) d += __shfl_xor_sync(0xFFFFFFFFu, d, off);
            best = fminf(best, d);
        }
        if (lane == 0) atomicMin(&g_minbits, __float_as_int(best));
    }

    grid_barrier();   // min + argmin complete

    // ---------------- Final: block 0 writes loss/scatter, re-arms ----------
    if (blockIdx.x == 0) {
        float loss = __int_as_float(g_minbits);
        long long pos = (long long)(unsigned)(g_argmin & 0xFFFFFFFFULL);
        if (tid == 0) out[0] = loss;
        if (loss <= 1.0f) {
            if (tid < CODE_LEN) out[OUT_MEM_OFF + pos * CODE_LEN + tid] = g_enc[tid];
            out[OUT_MD_OFF + pos * IN_DIM + tid] = x[tid];
            if (tid == 0) out[OUT_IDX_OFF + pos] = (float)count[0];
        }
        __syncthreads();
        g_colsum[tid] = 0.0f;
        g_colsq[tid]  = 0.0f;
        if (tid == 0) {
            g_minbits = 0x7f800000;
            g_argmin  = 0xFFFFFFFFFFFFFFFFULL;
        }
    }
}

extern "C" void kernel_launch(void* const* d_in, const int* in_sizes, int n_in,
                              void* d_out, int out_size) {
    const float* x        = (const float*)d_in[0];
    const float* memory   = (const float*)d_in[1];
    const float* mem_data = (const float*)d_in[2];
    const int*   mem_idx  = (const int*)d_in[3];
    const float* W        = (const float*)d_in[4];
    const float* b        = (const float*)d_in[5];
    const int*   count    = (const int*)d_in[6];

    fused<<<GRID, NTHREADS>>>(x, (const float4*)memory, (const float4*)mem_data,
                              mem_idx, W, b, count, (float*)d_out);
}